// round 10
// baseline (speedup 1.0000x reference)
#include <cuda_runtime.h>
#include <cuda_fp16.h>
#include <stdint.h>
#include <math.h>

#define TOKENS 8192
#define DDIM   1024
#define NEXP   8

#define BM 128
#define BN 128
#define BK 64
#define NKT (DDIM / BK)   // 16 k-chunks

// ---------------- scratch (allocation-free rule: __device__ globals) ----------------
__device__ int   g_cnt[NEXP];
__device__ int   g_tok[NEXP][TOKENS];    // packed: token*2 + slot
__device__ float g_wt [NEXP][TOKENS];
__device__ __half g_xh[TOKENS * DDIM];
__device__ __half g_Weh[NEXP * DDIM * DDIM];   // transposed: [e][n][k]
__device__ float g_scr[2 * TOKENS * DDIM];     // per-slot contributions

// ---------------- helpers ----------------
__device__ __forceinline__ uint32_t smem_u32(const void* p) {
    uint32_t a;
    asm("{ .reg .u64 t; cvta.to.shared.u64 t, %1; cvt.u32.u64 %0, t; }" : "=r"(a) : "l"(p));
    return a;
}

// SW128 swizzle for 128B rows (Swizzle<3,4,3>)
#define SWZ(o) ((o) ^ (((o) >> 3) & 0x70))

__device__ __forceinline__ void ldsm_x4(uint32_t* r, uint32_t addr) {
    asm volatile("ldmatrix.sync.aligned.m8n8.x4.shared.b16 {%0,%1,%2,%3}, [%4];"
                 : "=r"(r[0]), "=r"(r[1]), "=r"(r[2]), "=r"(r[3]) : "r"(addr));
}

__device__ __forceinline__ void mma_fp16(float* c, const uint32_t* a, uint32_t b0, uint32_t b1) {
    asm volatile("mma.sync.aligned.m16n8k16.row.col.f32.f16.f16.f32 "
                 "{%0,%1,%2,%3}, {%4,%5,%6,%7}, {%8,%9}, {%0,%1,%2,%3};"
                 : "+f"(c[0]), "+f"(c[1]), "+f"(c[2]), "+f"(c[3])
                 : "r"(a[0]), "r"(a[1]), "r"(a[2]), "r"(a[3]), "r"(b0), "r"(b1));
}

#define CP_ASYNC16(dst, src) \
    asm volatile("cp.async.cg.shared.global [%0], [%1], 16;" :: "r"(dst), "l"(src))
#define CP_COMMIT() asm volatile("cp.async.commit_group;" ::: "memory")
#define CP_WAIT(n)  asm volatile("cp.async.wait_group %0;" :: "n"(n) : "memory")

// ---------------- SMEM layout (GEMM) ----------------
#define SM_ENT   0
#define SM_W     512
#define SM_TILE  1024
#define A_BYTES  16384
#define STAGE_BYTES 32768
#define SMEM_TOTAL (SM_TILE + 2 * STAGE_BYTES)   // 66560

// ---------------- prep kernels ----------------
__global__ void zero_cnt_kernel() {
    if (threadIdx.x < NEXP) g_cnt[threadIdx.x] = 0;
}

// Fused: x fp32->fp16 conversion + gate scores + top-2 + bucket append.
// One block per token; thread tid covers d in [tid*4, tid*4+4).
__global__ __launch_bounds__(256)
void prep_gate_x(const float* __restrict__ x,
                 const float* __restrict__ Wg,
                 const float* __restrict__ bg) {
    __shared__ float red[8][NEXP];
    __shared__ float fin[NEXP];

    const int t   = blockIdx.x;
    const int tid = threadIdx.x;
    const int lane = tid & 31;
    const int wid  = tid >> 5;

    // read this token's 4 d-values once; convert + store fp16
    const int i = t * 256 + tid;
    float4 v = reinterpret_cast<const float4*>(x)[i];
    __half2 h01 = __float22half2_rn(make_float2(v.x, v.y));
    __half2 h23 = __float22half2_rn(make_float2(v.z, v.w));
    reinterpret_cast<uint2*>(g_xh)[i] =
        make_uint2(*reinterpret_cast<uint32_t*>(&h01), *reinterpret_cast<uint32_t*>(&h23));

    // gate partials from the same registers
    float s[NEXP];
#pragma unroll
    for (int e = 0; e < NEXP; e++) s[e] = 0.f;
    float xv[4] = {v.x, v.y, v.z, v.w};
#pragma unroll
    for (int j = 0; j < 4; j++) {
        const float4* wr = reinterpret_cast<const float4*>(Wg + (size_t)(tid * 4 + j) * NEXP);
        float4 w0 = wr[0], w1 = wr[1];
        s[0] += xv[j] * w0.x; s[1] += xv[j] * w0.y;
        s[2] += xv[j] * w0.z; s[3] += xv[j] * w0.w;
        s[4] += xv[j] * w1.x; s[5] += xv[j] * w1.y;
        s[6] += xv[j] * w1.z; s[7] += xv[j] * w1.w;
    }
#pragma unroll
    for (int e = 0; e < NEXP; e++) {
#pragma unroll
        for (int o = 16; o > 0; o >>= 1)
            s[e] += __shfl_down_sync(0xffffffffu, s[e], o);
    }
    if (lane == 0) {
#pragma unroll
        for (int e = 0; e < NEXP; e++) red[wid][e] = s[e];
    }
    __syncthreads();
    if (tid < NEXP) {
        float r = 0.f;
#pragma unroll
        for (int w = 0; w < 8; w++) r += red[w][tid];
        fin[tid] = r + bg[tid];
    }
    __syncthreads();

    if (tid == 0) {
        float v1 = -INFINITY, v2 = -INFINITY;
        int   i1 = 0, i2 = 0;
#pragma unroll
        for (int e = 0; e < NEXP; e++) {
            float sc = fin[e];
            if (sc > v1)      { v2 = v1; i2 = i1; v1 = sc; i1 = e; }
            else if (sc > v2) { v2 = sc; i2 = e; }
        }
        float l     = __expf(v2 - v1);
        float denom = 1.f + l;
        int p1 = atomicAdd(&g_cnt[i1], 1);
        g_tok[i1][p1] = t * 2 + 0; g_wt[i1][p1] = 1.f / denom;
        int p2 = atomicAdd(&g_cnt[i2], 1);
        g_tok[i2][p2] = t * 2 + 1; g_wt[i2][p2] = l / denom;
    }
}

__global__ void prep_we_kernel(const float* __restrict__ We) {
    __shared__ float s[32][33];
    const int e  = blockIdx.z;
    const int n0 = blockIdx.x * 32;
    const int k0 = blockIdx.y * 32;
    const int tx = threadIdx.x & 31;
    const int ty = threadIdx.x >> 5;   // 0..7
    const float* src = We + ((size_t)e * DDIM + k0) * DDIM + n0;
#pragma unroll
    for (int i = 0; i < 4; i++)
        s[ty + i * 8][tx] = src[(size_t)(ty + i * 8) * DDIM + tx];
    __syncthreads();
#pragma unroll
    for (int i = 0; i < 4; i++) {
        const int nn = ty + i * 8;
        size_t o = ((size_t)e * DDIM + n0 + nn) * DDIM + k0 + tx;
        g_Weh[o] = __float2half_rn(s[tx][nn]);
    }
}

// ---------------- HMMA grouped GEMM (fp16, 2-stage cp.async, 2 CTAs/SM) ----------------
__global__ __launch_bounds__(256, 2)
void moe_gemm_mma(const float* __restrict__ be) {
    const int e    = blockIdx.z;
    const int n    = g_cnt[e];
    const int row0 = blockIdx.x * BM;
    if (row0 >= n) return;
    const int col0   = blockIdx.y * BN;
    const int nvalid = min(BM, n - row0);

    extern __shared__ char smem[];
    int*   ent_s = (int*)(smem + SM_ENT);
    float* w_s   = (float*)(smem + SM_W);
    const uint32_t tiles_u = smem_u32(smem + SM_TILE);

    const int tid  = threadIdx.x;
    const int lane = tid & 31;
    const int wid  = tid >> 5;

    if (tid < BM) {
        int tk = 0; float w = 0.f;
        if (tid < nvalid) { tk = g_tok[e][row0 + tid]; w = g_wt[e][row0 + tid]; }
        ent_s[tid] = tk;
        w_s[tid]   = w;
    }
    __syncthreads();

    // ---- staging: thread covers granules (sh..sh+3) of A row sr and B row sr
    const int sr = tid >> 1;
    const int sh = (tid & 1) * 4;
    uint32_t og[4];
#pragma unroll
    for (int q = 0; q < 4; q++)
        og[q] = SWZ((uint32_t)(sr * 128 + (sh + q) * 16));

    const __half* aS = g_xh + (size_t)(ent_s[sr] >> 1) * DDIM + sh * 8;
    const __half* bS = g_Weh + ((size_t)e * DDIM + col0 + sr) * DDIM + sh * 8;

    // ---- compute assignment: warp tile 64x32
    const int m0  = (wid & 1) * 64;
    const int n0w = (wid >> 1) * 32;
    const int a_lrow = (lane & 7) + ((lane >> 3) & 1) * 8;
    const int a_lk   = ((lane >> 4) & 1) * 8;
    const int b_lrow = (lane & 7) + ((lane >> 4) & 1) * 8;
    const int b_lk   = ((lane >> 3) & 1) * 8;

    float acc[4][4][4];
#pragma unroll
    for (int i = 0; i < 4; i++)
#pragma unroll
        for (int j = 0; j < 4; j++)
#pragma unroll
            for (int q = 0; q < 4; q++) acc[i][j][q] = 0.f;

    // prologue: stage chunk 0
    {
#pragma unroll
        for (int q = 0; q < 4; q++) CP_ASYNC16(tiles_u + og[q], aS + q * 8);
#pragma unroll
        for (int q = 0; q < 4; q++) CP_ASYNC16(tiles_u + A_BYTES + og[q], bS + q * 8);
        CP_COMMIT();
    }

    for (int kt = 0; kt < NKT; kt++) {
        if (kt + 1 < NKT) {
            const uint32_t base = tiles_u + ((kt + 1) & 1) * STAGE_BYTES;
            const int kk = (kt + 1) * BK;
#pragma unroll
            for (int q = 0; q < 4; q++) CP_ASYNC16(base + og[q], aS + kk + q * 8);
#pragma unroll
            for (int q = 0; q < 4; q++) CP_ASYNC16(base + A_BYTES + og[q], bS + kk + q * 8);
            CP_COMMIT();
            CP_WAIT(1);            // chunk kt complete
        } else {
            CP_WAIT(0);
        }
        __syncthreads();

        const uint32_t AU = tiles_u + (kt & 1) * STAGE_BYTES;
        const uint32_t BU = AU + A_BYTES;
#pragma unroll
        for (int ks = 0; ks < 4; ks++) {
            uint32_t ah[4][4], bh[2][4];
#pragma unroll
            for (int mt = 0; mt < 4; mt++) {
                const uint32_t o = SWZ((uint32_t)((m0 + mt * 16 + a_lrow) * 128 +
                                                  (ks * 16 + a_lk) * 2));
                ldsm_x4(ah[mt], AU + o);
            }
#pragma unroll
            for (int np = 0; np < 2; np++) {
                const uint32_t o = SWZ((uint32_t)((n0w + np * 16 + b_lrow) * 128 +
                                                  (ks * 16 + b_lk) * 2));
                ldsm_x4(bh[np], BU + o);
            }
#pragma unroll
            for (int mt = 0; mt < 4; mt++)
#pragma unroll
                for (int nt = 0; nt < 4; nt++) {
                    const int bp = nt >> 1, bo = (nt & 1) * 2;
                    mma_fp16(acc[mt][nt], ah[mt], bh[bp][bo], bh[bp][bo + 1]);
                }
        }
        __syncthreads();   // chunk kt consumed by all warps before restage
    }

    // ---- epilogue: scr[slot][token][col] = w * (acc + be[e][col]), plain stores
    const int gid = lane >> 2;
    const int tig = lane & 3;
    const float* beRow = be + (size_t)e * DDIM + col0;
#pragma unroll
    for (int mt = 0; mt < 4; mt++) {
        const int  rA = m0 + mt * 16 + gid;
        const int  rB = rA + 8;
        const bool vA = rA < nvalid;
        const bool vB = rB < nvalid;
        const int  entA = ent_s[rA];
        const int  entB = ent_s[rB];
        const float wA = w_s[rA];
        const float wB = w_s[rB];
        float* sA = g_scr + ((size_t)(entA >> 1) + (size_t)(entA & 1) * TOKENS) * DDIM + col0;
        float* sB = g_scr + ((size_t)(entB >> 1) + (size_t)(entB & 1) * TOKENS) * DDIM + col0;
#pragma unroll
        for (int nt = 0; nt < 4; nt++) {
            const int c = n0w + nt * 8 + tig * 2;
            const float2 bev = *reinterpret_cast<const float2*>(beRow + c);
            if (vA) {
                float2 v = make_float2(wA * (acc[mt][nt][0] + bev.x),
                                       wA * (acc[mt][nt][1] + bev.y));
                *reinterpret_cast<float2*>(sA + c) = v;
            }
            if (vB) {
                float2 v = make_float2(wB * (acc[mt][nt][2] + bev.x),
                                       wB * (acc[mt][nt][3] + bev.y));
                *reinterpret_cast<float2*>(sB + c) = v;
            }
        }
    }
}

__global__ void combine_kernel(float* __restrict__ out) {
    const size_t i = (size_t)blockIdx.x * 256 + threadIdx.x;   // float4 units
    const float4* s = reinterpret_cast<const float4*>(g_scr);
    float4 a = s[i];
    float4 b = s[i + (size_t)TOKENS * DDIM / 4];
    a.x += b.x; a.y += b.y; a.z += b.z; a.w += b.w;
    reinterpret_cast<float4*>(out)[i] = a;
}

// ---------------- launch ----------------
extern "C" void kernel_launch(void* const* d_in, const int* in_sizes, int n_in,
                              void* d_out, int out_size) {
    const float* x  = (const float*)d_in[0];
    const float* Wg = (const float*)d_in[1];
    const float* bg = (const float*)d_in[2];
    const float* We = (const float*)d_in[3];
    const float* be = (const float*)d_in[4];
    float* out = (float*)d_out;

    cudaFuncSetAttribute(moe_gemm_mma, cudaFuncAttributeMaxDynamicSharedMemorySize, SMEM_TOTAL);

    zero_cnt_kernel<<<1, 32>>>();
    prep_we_kernel<<<dim3(DDIM / 32, DDIM / 32, NEXP), 256>>>(We);
    prep_gate_x<<<TOKENS, 256>>>(x, Wg, bg);          // fused convert + gate

    dim3 grid(TOKENS / BM, DDIM / BN, NEXP);   // (64, 8, 8); empty row tiles early-exit
    moe_gemm_mma<<<grid, 256, SMEM_TOTAL>>>(be);

    combine_kernel<<<TOKENS * DDIM / 4 / 256, 256>>>(out);
}

// round 11
// speedup vs baseline: 1.2106x; 1.2106x over previous
#include <cuda_runtime.h>
#include <cuda_fp16.h>
#include <stdint.h>
#include <math.h>

#define TOKENS 8192
#define DDIM   1024
#define NEXP   8

#define BM 128
#define BN 128
#define BK 64
#define NKT (DDIM / BK)   // 16 k-chunks

// ---------------- scratch (allocation-free rule: __device__ globals) ----------------
__device__ int   g_cnt[NEXP];
__device__ int   g_tok[NEXP][TOKENS];    // packed: token*2 + slot
__device__ float g_wt [NEXP][TOKENS];
__device__ __half g_xh[TOKENS * DDIM];
__device__ __half g_Weh[NEXP * DDIM * DDIM];   // transposed: [e][n][k]
__device__ float g_scr[2 * TOKENS * DDIM];     // per-slot contributions

// ---------------- helpers ----------------
__device__ __forceinline__ uint32_t smem_u32(const void* p) {
    uint32_t a;
    asm("{ .reg .u64 t; cvta.to.shared.u64 t, %1; cvt.u32.u64 %0, t; }" : "=r"(a) : "l"(p));
    return a;
}

// SW128 swizzle for 128B rows (Swizzle<3,4,3>)
#define SWZ(o) ((o) ^ (((o) >> 3) & 0x70))

__device__ __forceinline__ void ldsm_x4(uint32_t* r, uint32_t addr) {
    asm volatile("ldmatrix.sync.aligned.m8n8.x4.shared.b16 {%0,%1,%2,%3}, [%4];"
                 : "=r"(r[0]), "=r"(r[1]), "=r"(r[2]), "=r"(r[3]) : "r"(addr));
}

__device__ __forceinline__ void mma_fp16(float* c, const uint32_t* a, uint32_t b0, uint32_t b1) {
    asm volatile("mma.sync.aligned.m16n8k16.row.col.f32.f16.f16.f32 "
                 "{%0,%1,%2,%3}, {%4,%5,%6,%7}, {%8,%9}, {%0,%1,%2,%3};"
                 : "+f"(c[0]), "+f"(c[1]), "+f"(c[2]), "+f"(c[3])
                 : "r"(a[0]), "r"(a[1]), "r"(a[2]), "r"(a[3]), "r"(b0), "r"(b1));
}

#define CP_ASYNC16(dst, src) \
    asm volatile("cp.async.cg.shared.global [%0], [%1], 16;" :: "r"(dst), "l"(src))
#define CP_COMMIT() asm volatile("cp.async.commit_group;" ::: "memory")
#define CP_WAIT(n)  asm volatile("cp.async.wait_group %0;" :: "n"(n) : "memory")

// ---------------- SMEM layout (GEMM): 3 stages ----------------
#define SM_ENT   0
#define SM_W     512
#define SM_TILE  1024
#define A_BYTES  16384
#define STAGE_BYTES 32768
#define SMEM_TOTAL (SM_TILE + 3 * STAGE_BYTES)   // 99328; x2 CTAs = 198656 < 228KB

// ---------------- prep kernels ----------------
__global__ void zero_cnt_kernel() {
    if (threadIdx.x < NEXP) g_cnt[threadIdx.x] = 0;
}

// Fused gate + x fp32->fp16: warp handles 2 tokens, Wg slab in registers.
__global__ __launch_bounds__(256)
void gate_convert_kernel(const float* __restrict__ x,
                         const float* __restrict__ Wg,
                         const float* __restrict__ bg) {
    const int warp = threadIdx.x >> 5;
    const int lane = threadIdx.x & 31;
    const int t0 = (blockIdx.x * 8 + warp) * 2;

    float acc[2][NEXP];
#pragma unroll
    for (int tt = 0; tt < 2; tt++)
#pragma unroll
        for (int e = 0; e < NEXP; e++) acc[tt][e] = 0.f;

#pragma unroll
    for (int s = 0; s < 4; s++) {      // 4 slabs of 256 d
        float wg[8][NEXP];
#pragma unroll
        for (int i = 0; i < 8; i++) {
            const float4* wr = reinterpret_cast<const float4*>(
                Wg + (size_t)(s * 256 + i * 32 + lane) * NEXP);
            float4 w0 = wr[0], w1 = wr[1];
            wg[i][0] = w0.x; wg[i][1] = w0.y; wg[i][2] = w0.z; wg[i][3] = w0.w;
            wg[i][4] = w1.x; wg[i][5] = w1.y; wg[i][6] = w1.z; wg[i][7] = w1.w;
        }
#pragma unroll
        for (int tt = 0; tt < 2; tt++) {
            const int dbase = s * 256 + lane;
            const float* xr = x + (size_t)(t0 + tt) * DDIM + dbase;
            __half*      xo = g_xh + (size_t)(t0 + tt) * DDIM + dbase;
#pragma unroll
            for (int i = 0; i < 8; i++) {
                float xv = xr[i * 32];
                xo[i * 32] = __float2half_rn(xv);      // fused conversion store
#pragma unroll
                for (int e = 0; e < NEXP; e++) acc[tt][e] += xv * wg[i][e];
            }
        }
    }

#pragma unroll
    for (int tt = 0; tt < 2; tt++) {
        float v[NEXP];
#pragma unroll
        for (int e = 0; e < NEXP; e++) {
            float r = acc[tt][e];
#pragma unroll
            for (int o = 16; o > 0; o >>= 1) r += __shfl_down_sync(0xffffffffu, r, o);
            v[e] = r;
        }
        if (lane == 0) {
            float v1 = -INFINITY, v2 = -INFINITY;
            int   i1 = 0, i2 = 0;
#pragma unroll
            for (int e = 0; e < NEXP; e++) {
                float s2 = v[e] + bg[e];
                if (s2 > v1)      { v2 = v1; i2 = i1; v1 = s2; i1 = e; }
                else if (s2 > v2) { v2 = s2; i2 = e; }
            }
            float l     = __expf(v2 - v1);
            float denom = 1.f + l;
            const int t = t0 + tt;
            int p1 = atomicAdd(&g_cnt[i1], 1);
            g_tok[i1][p1] = t * 2 + 0; g_wt[i1][p1] = 1.f / denom;
            int p2 = atomicAdd(&g_cnt[i2], 1);
            g_tok[i2][p2] = t * 2 + 1; g_wt[i2][p2] = l / denom;
        }
    }
}

__global__ void prep_we_kernel(const float* __restrict__ We) {
    __shared__ float s[32][33];
    const int e  = blockIdx.z;
    const int n0 = blockIdx.x * 32;
    const int k0 = blockIdx.y * 32;
    const int tx = threadIdx.x & 31;
    const int ty = threadIdx.x >> 5;   // 0..7
    const float* src = We + ((size_t)e * DDIM + k0) * DDIM + n0;
#pragma unroll
    for (int i = 0; i < 4; i++)
        s[ty + i * 8][tx] = src[(size_t)(ty + i * 8) * DDIM + tx];
    __syncthreads();
#pragma unroll
    for (int i = 0; i < 4; i++) {
        const int nn = ty + i * 8;
        size_t o = ((size_t)e * DDIM + n0 + nn) * DDIM + k0 + tx;
        g_Weh[o] = __float2half_rn(s[tx][nn]);
    }
}

// ---------------- HMMA grouped GEMM (fp16, 3-stage cp.async, 1 barrier/chunk, 2 CTAs/SM) ----
__global__ __launch_bounds__(256, 2)
void moe_gemm_mma(const float* __restrict__ be) {
    const int e    = blockIdx.z;
    const int n    = g_cnt[e];
    const int row0 = blockIdx.x * BM;
    if (row0 >= n) return;
    const int col0   = blockIdx.y * BN;
    const int nvalid = min(BM, n - row0);

    extern __shared__ char smem[];
    int*   ent_s = (int*)(smem + SM_ENT);
    float* w_s   = (float*)(smem + SM_W);
    const uint32_t tiles_u = smem_u32(smem + SM_TILE);

    const int tid  = threadIdx.x;
    const int lane = tid & 31;
    const int wid  = tid >> 5;

    if (tid < BM) {
        int tk = 0; float w = 0.f;
        if (tid < nvalid) { tk = g_tok[e][row0 + tid]; w = g_wt[e][row0 + tid]; }
        ent_s[tid] = tk;
        w_s[tid]   = w;
    }
    __syncthreads();

    // ---- staging: thread covers granules (sh..sh+3) of A row sr and B row sr
    const int sr = tid >> 1;
    const int sh = (tid & 1) * 4;
    uint32_t og[4];
#pragma unroll
    for (int q = 0; q < 4; q++)
        og[q] = SWZ((uint32_t)(sr * 128 + (sh + q) * 16));

    const __half* aS = g_xh + (size_t)(ent_s[sr] >> 1) * DDIM + sh * 8;
    const __half* bS = g_Weh + ((size_t)e * DDIM + col0 + sr) * DDIM + sh * 8;

    // ---- compute assignment: warp tile 64x32
    const int m0  = (wid & 1) * 64;
    const int n0w = (wid >> 1) * 32;
    const int a_lrow = (lane & 7) + ((lane >> 3) & 1) * 8;
    const int a_lk   = ((lane >> 4) & 1) * 8;
    const int b_lrow = (lane & 7) + ((lane >> 4) & 1) * 8;
    const int b_lk   = ((lane >> 3) & 1) * 8;

    float acc[4][4][4];
#pragma unroll
    for (int i = 0; i < 4; i++)
#pragma unroll
        for (int j = 0; j < 4; j++)
#pragma unroll
            for (int q = 0; q < 4; q++) acc[i][j][q] = 0.f;

    // prologue: stage chunks 0,1
#pragma unroll
    for (int pc = 0; pc < 2; pc++) {
        const uint32_t base = tiles_u + pc * STAGE_BYTES;
        const int kk = pc * BK;
#pragma unroll
        for (int q = 0; q < 4; q++) CP_ASYNC16(base + og[q], aS + kk + q * 8);
#pragma unroll
        for (int q = 0; q < 4; q++) CP_ASYNC16(base + A_BYTES + og[q], bS + kk + q * 8);
        CP_COMMIT();
    }

    for (int kt = 0; kt < NKT; kt++) {
        if (kt + 1 < NKT) { CP_WAIT(1); } else { CP_WAIT(0); }
        __syncthreads();   // single barrier: chunk kt visible; all warps past chunk kt-1

        // restage chunk kt+2 into buffer (kt+2)%3 == (kt-1)%3 (freed by the barrier)
        if (kt + 2 < NKT) {
            const uint32_t base = tiles_u + ((kt + 2) % 3) * STAGE_BYTES;
            const int kk = (kt + 2) * BK;
#pragma unroll
            for (int q = 0; q < 4; q++) CP_ASYNC16(base + og[q], aS + kk + q * 8);
#pragma unroll
            for (int q = 0; q < 4; q++) CP_ASYNC16(base + A_BYTES + og[q], bS + kk + q * 8);
            CP_COMMIT();
        }

        const uint32_t AU = tiles_u + (kt % 3) * STAGE_BYTES;
        const uint32_t BU = AU + A_BYTES;
#pragma unroll
        for (int ks = 0; ks < 4; ks++) {
            uint32_t ah[4][4], bh[2][4];
#pragma unroll
            for (int mt = 0; mt < 4; mt++) {
                const uint32_t o = SWZ((uint32_t)((m0 + mt * 16 + a_lrow) * 128 +
                                                  (ks * 16 + a_lk) * 2));
                ldsm_x4(ah[mt], AU + o);
            }
#pragma unroll
            for (int np = 0; np < 2; np++) {
                const uint32_t o = SWZ((uint32_t)((n0w + np * 16 + b_lrow) * 128 +
                                                  (ks * 16 + b_lk) * 2));
                ldsm_x4(bh[np], BU + o);
            }
#pragma unroll
            for (int mt = 0; mt < 4; mt++)
#pragma unroll
                for (int nt = 0; nt < 4; nt++) {
                    const int bp = nt >> 1, bo = (nt & 1) * 2;
                    mma_fp16(acc[mt][nt], ah[mt], bh[bp][bo], bh[bp][bo + 1]);
                }
        }
    }

    // ---- epilogue: scr[slot][token][col] = w * (acc + be[e][col]), plain stores
    const int gid = lane >> 2;
    const int tig = lane & 3;
    const float* beRow = be + (size_t)e * DDIM + col0;
#pragma unroll
    for (int mt = 0; mt < 4; mt++) {
        const int  rA = m0 + mt * 16 + gid;
        const int  rB = rA + 8;
        const bool vA = rA < nvalid;
        const bool vB = rB < nvalid;
        const int  entA = ent_s[rA];
        const int  entB = ent_s[rB];
        const float wA = w_s[rA];
        const float wB = w_s[rB];
        float* sA = g_scr + ((size_t)(entA >> 1) + (size_t)(entA & 1) * TOKENS) * DDIM + col0;
        float* sB = g_scr + ((size_t)(entB >> 1) + (size_t)(entB & 1) * TOKENS) * DDIM + col0;
#pragma unroll
        for (int nt = 0; nt < 4; nt++) {
            const int c = n0w + nt * 8 + tig * 2;
            const float2 bev = *reinterpret_cast<const float2*>(beRow + c);
            if (vA) {
                float2 v = make_float2(wA * (acc[mt][nt][0] + bev.x),
                                       wA * (acc[mt][nt][1] + bev.y));
                *reinterpret_cast<float2*>(sA + c) = v;
            }
            if (vB) {
                float2 v = make_float2(wB * (acc[mt][nt][2] + bev.x),
                                       wB * (acc[mt][nt][3] + bev.y));
                *reinterpret_cast<float2*>(sB + c) = v;
            }
        }
    }
}

__global__ void combine_kernel(float* __restrict__ out) {
    const size_t i = (size_t)blockIdx.x * 256 + threadIdx.x;   // float4 units
    const float4* s = reinterpret_cast<const float4*>(g_scr);
    float4 a = s[i];
    float4 b = s[i + (size_t)TOKENS * DDIM / 4];
    a.x += b.x; a.y += b.y; a.z += b.z; a.w += b.w;
    reinterpret_cast<float4*>(out)[i] = a;
}

// ---------------- launch ----------------
extern "C" void kernel_launch(void* const* d_in, const int* in_sizes, int n_in,
                              void* d_out, int out_size) {
    const float* x  = (const float*)d_in[0];
    const float* Wg = (const float*)d_in[1];
    const float* bg = (const float*)d_in[2];
    const float* We = (const float*)d_in[3];
    const float* be = (const float*)d_in[4];
    float* out = (float*)d_out;

    cudaFuncSetAttribute(moe_gemm_mma, cudaFuncAttributeMaxDynamicSharedMemorySize, SMEM_TOTAL);

    zero_cnt_kernel<<<1, 32>>>();
    prep_we_kernel<<<dim3(DDIM / 32, DDIM / 32, NEXP), 256>>>(We);
    gate_convert_kernel<<<TOKENS / 16, 256>>>(x, Wg, bg);   // fused gate + fp16 convert

    dim3 grid(TOKENS / BM, DDIM / BN, NEXP);   // (64, 8, 8); empty row tiles early-exit
    moe_gemm_mma<<<grid, 256, SMEM_TOTAL>>>(be);

    combine_kernel<<<TOKENS * DDIM / 4 / 256, 256>>>(out);
}

// round 12
// speedup vs baseline: 1.2391x; 1.0235x over previous
#include <cuda_runtime.h>
#include <cuda_fp16.h>
#include <stdint.h>
#include <math.h>

#define TOKENS 8192
#define DDIM   1024
#define NEXP   8

#define BM 128
#define BN 128
#define BK 64
#define NKT (DDIM / BK)   // 16 k-chunks

// ---------------- scratch (allocation-free rule: __device__ globals) ----------------
__device__ int   g_cnt[NEXP];
__device__ int   g_tok[NEXP][TOKENS];    // packed: token*2 + slot
__device__ float g_wt [NEXP][TOKENS];
__device__ __half g_xh[TOKENS * DDIM];
__device__ __half g_Weh[NEXP * DDIM * DDIM];   // transposed: [e][n][k]
__device__ float g_scr[2 * TOKENS * DDIM];     // per-slot contributions

// ---------------- helpers ----------------
__device__ __forceinline__ uint32_t smem_u32(const void* p) {
    uint32_t a;
    asm("{ .reg .u64 t; cvta.to.shared.u64 t, %1; cvt.u32.u64 %0, t; }" : "=r"(a) : "l"(p));
    return a;
}

// SW128 swizzle for 128B rows (Swizzle<3,4,3>)
#define SWZ(o) ((o) ^ (((o) >> 3) & 0x70))

__device__ __forceinline__ void ldsm_x4(uint32_t* r, uint32_t addr) {
    asm volatile("ldmatrix.sync.aligned.m8n8.x4.shared.b16 {%0,%1,%2,%3}, [%4];"
                 : "=r"(r[0]), "=r"(r[1]), "=r"(r[2]), "=r"(r[3]) : "r"(addr));
}

__device__ __forceinline__ void mma_fp16(float* c, const uint32_t* a, uint32_t b0, uint32_t b1) {
    asm volatile("mma.sync.aligned.m16n8k16.row.col.f32.f16.f16.f32 "
                 "{%0,%1,%2,%3}, {%4,%5,%6,%7}, {%8,%9}, {%0,%1,%2,%3};"
                 : "+f"(c[0]), "+f"(c[1]), "+f"(c[2]), "+f"(c[3])
                 : "r"(a[0]), "r"(a[1]), "r"(a[2]), "r"(a[3]), "r"(b0), "r"(b1));
}

#define CP_ASYNC16(dst, src) \
    asm volatile("cp.async.cg.shared.global [%0], [%1], 16;" :: "r"(dst), "l"(src))
#define CP_COMMIT() asm volatile("cp.async.commit_group;" ::: "memory")
#define CP_WAIT(n)  asm volatile("cp.async.wait_group %0;" :: "n"(n) : "memory")

// ---------------- SMEM layout (GEMM): 3 stages ----------------
#define SM_ENT   0
#define SM_W     512
#define SM_TILE  1024
#define A_BYTES  16384
#define STAGE_BYTES 32768
#define SMEM_TOTAL (SM_TILE + 3 * STAGE_BYTES)   // 99328; x2 CTAs = 198656 < 228KB

// ---------------- prep kernels ----------------
// Fused gate + x fp32->fp16: warp handles 2 tokens, Wg slab in registers.
__global__ __launch_bounds__(256)
void gate_convert_kernel(const float* __restrict__ x,
                         const float* __restrict__ Wg,
                         const float* __restrict__ bg) {
    const int warp = threadIdx.x >> 5;
    const int lane = threadIdx.x & 31;
    const int t0 = (blockIdx.x * 8 + warp) * 2;

    float acc[2][NEXP];
#pragma unroll
    for (int tt = 0; tt < 2; tt++)
#pragma unroll
        for (int e = 0; e < NEXP; e++) acc[tt][e] = 0.f;

#pragma unroll
    for (int s = 0; s < 4; s++) {      // 4 slabs of 256 d
        float wg[8][NEXP];
#pragma unroll
        for (int i = 0; i < 8; i++) {
            const float4* wr = reinterpret_cast<const float4*>(
                Wg + (size_t)(s * 256 + i * 32 + lane) * NEXP);
            float4 w0 = wr[0], w1 = wr[1];
            wg[i][0] = w0.x; wg[i][1] = w0.y; wg[i][2] = w0.z; wg[i][3] = w0.w;
            wg[i][4] = w1.x; wg[i][5] = w1.y; wg[i][6] = w1.z; wg[i][7] = w1.w;
        }
#pragma unroll
        for (int tt = 0; tt < 2; tt++) {
            const int dbase = s * 256 + lane;
            const float* xr = x + (size_t)(t0 + tt) * DDIM + dbase;
            __half*      xo = g_xh + (size_t)(t0 + tt) * DDIM + dbase;
#pragma unroll
            for (int i = 0; i < 8; i++) {
                float xv = xr[i * 32];
                xo[i * 32] = __float2half_rn(xv);      // fused conversion store
#pragma unroll
                for (int e = 0; e < NEXP; e++) acc[tt][e] += xv * wg[i][e];
            }
        }
    }

#pragma unroll
    for (int tt = 0; tt < 2; tt++) {
        float v[NEXP];
#pragma unroll
        for (int e = 0; e < NEXP; e++) {
            float r = acc[tt][e];
#pragma unroll
            for (int o = 16; o > 0; o >>= 1) r += __shfl_down_sync(0xffffffffu, r, o);
            v[e] = r;
        }
        if (lane == 0) {
            float v1 = -INFINITY, v2 = -INFINITY;
            int   i1 = 0, i2 = 0;
#pragma unroll
            for (int e = 0; e < NEXP; e++) {
                float s2 = v[e] + bg[e];
                if (s2 > v1)      { v2 = v1; i2 = i1; v1 = s2; i1 = e; }
                else if (s2 > v2) { v2 = s2; i2 = e; }
            }
            float l     = __expf(v2 - v1);
            float denom = 1.f + l;
            const int t = t0 + tt;
            int p1 = atomicAdd(&g_cnt[i1], 1);
            g_tok[i1][p1] = t * 2 + 0; g_wt[i1][p1] = 1.f / denom;
            int p2 = atomicAdd(&g_cnt[i2], 1);
            g_tok[i2][p2] = t * 2 + 1; g_wt[i2][p2] = l / denom;
        }
    }
}

// We transpose+convert; block (0,0,0) also zeroes g_cnt (ordered before gate by stream)
__global__ void prep_we_kernel(const float* __restrict__ We) {
    __shared__ float s[32][33];
    if (blockIdx.x == 0 && blockIdx.y == 0 && blockIdx.z == 0 && threadIdx.x < NEXP)
        g_cnt[threadIdx.x] = 0;
    const int e  = blockIdx.z;
    const int n0 = blockIdx.x * 32;
    const int k0 = blockIdx.y * 32;
    const int tx = threadIdx.x & 31;
    const int ty = threadIdx.x >> 5;   // 0..7
    const float* src = We + ((size_t)e * DDIM + k0) * DDIM + n0;
#pragma unroll
    for (int i = 0; i < 4; i++)
        s[ty + i * 8][tx] = src[(size_t)(ty + i * 8) * DDIM + tx];
    __syncthreads();
#pragma unroll
    for (int i = 0; i < 4; i++) {
        const int nn = ty + i * 8;
        size_t o = ((size_t)e * DDIM + n0 + nn) * DDIM + k0 + tx;
        g_Weh[o] = __float2half_rn(s[tx][nn]);
    }
}

// ---------------- HMMA grouped GEMM (fp16, 3-stage cp.async, warp-staggered ks) ----------
__global__ __launch_bounds__(256, 2)
void moe_gemm_mma(const float* __restrict__ be) {
    const int e    = blockIdx.z;
    const int n    = g_cnt[e];
    const int row0 = blockIdx.x * BM;
    if (row0 >= n) return;
    const int col0   = blockIdx.y * BN;
    const int nvalid = min(BM, n - row0);

    extern __shared__ char smem[];
    int*   ent_s = (int*)(smem + SM_ENT);
    float* w_s   = (float*)(smem + SM_W);
    const uint32_t tiles_u = smem_u32(smem + SM_TILE);

    const int tid  = threadIdx.x;
    const int lane = tid & 31;
    const int wid  = tid >> 5;

    if (tid < BM) {
        int tk = 0; float w = 0.f;
        if (tid < nvalid) { tk = g_tok[e][row0 + tid]; w = g_wt[e][row0 + tid]; }
        ent_s[tid] = tk;
        w_s[tid]   = w;
    }
    __syncthreads();

    // ---- staging: thread covers granules (sh..sh+3) of A row sr and B row sr
    const int sr = tid >> 1;
    const int sh = (tid & 1) * 4;
    uint32_t og[4];
#pragma unroll
    for (int q = 0; q < 4; q++)
        og[q] = SWZ((uint32_t)(sr * 128 + (sh + q) * 16));

    const __half* aS = g_xh + (size_t)(ent_s[sr] >> 1) * DDIM + sh * 8;
    const __half* bS = g_Weh + ((size_t)e * DDIM + col0 + sr) * DDIM + sh * 8;

    // ---- compute assignment: warp tile 64x32
    const int m0  = (wid & 1) * 64;
    const int n0w = (wid >> 1) * 32;
    const int a_lrow = (lane & 7) + ((lane >> 3) & 1) * 8;
    const int a_lk   = ((lane >> 4) & 1) * 8;
    const int b_lrow = (lane & 7) + ((lane >> 4) & 1) * 8;
    const int b_lk   = ((lane >> 3) & 1) * 8;

    float acc[4][4][4];
#pragma unroll
    for (int i = 0; i < 4; i++)
#pragma unroll
        for (int j = 0; j < 4; j++)
#pragma unroll
            for (int q = 0; q < 4; q++) acc[i][j][q] = 0.f;

    // prologue: stage chunks 0,1
#pragma unroll
    for (int pc = 0; pc < 2; pc++) {
        const uint32_t base = tiles_u + pc * STAGE_BYTES;
        const int kk = pc * BK;
#pragma unroll
        for (int q = 0; q < 4; q++) CP_ASYNC16(base + og[q], aS + kk + q * 8);
#pragma unroll
        for (int q = 0; q < 4; q++) CP_ASYNC16(base + A_BYTES + og[q], bS + kk + q * 8);
        CP_COMMIT();
    }

    const int ksPhase = wid & 3;   // de-phase warps: stagger ks order per warp

    for (int kt = 0; kt < NKT; kt++) {
        if (kt + 1 < NKT) { CP_WAIT(1); } else { CP_WAIT(0); }
        __syncthreads();   // chunk kt visible; all warps past chunk kt-1

        // restage chunk kt+2 into buffer (kt+2)%3 == (kt-1)%3 (freed by the barrier)
        if (kt + 2 < NKT) {
            const uint32_t base = tiles_u + ((kt + 2) % 3) * STAGE_BYTES;
            const int kk = (kt + 2) * BK;
#pragma unroll
            for (int q = 0; q < 4; q++) CP_ASYNC16(base + og[q], aS + kk + q * 8);
#pragma unroll
            for (int q = 0; q < 4; q++) CP_ASYNC16(base + A_BYTES + og[q], bS + kk + q * 8);
            CP_COMMIT();
        }

        const uint32_t AU = tiles_u + (kt % 3) * STAGE_BYTES;
        const uint32_t BU = AU + A_BYTES;
#pragma unroll
        for (int ksi = 0; ksi < 4; ksi++) {
            const int ks = (ksi + ksPhase) & 3;    // rotated k-sub order (commutative sum)
            uint32_t ah[4][4], bh[2][4];
#pragma unroll
            for (int np = 0; np < 2; np++) {
                const uint32_t o = SWZ((uint32_t)((n0w + np * 16 + b_lrow) * 128 +
                                                  (ks * 16 + b_lk) * 2));
                ldsm_x4(bh[np], BU + o);
            }
#pragma unroll
            for (int mt = 0; mt < 4; mt++) {
                const uint32_t o = SWZ((uint32_t)((m0 + mt * 16 + a_lrow) * 128 +
                                                  (ks * 16 + a_lk) * 2));
                ldsm_x4(ah[mt], AU + o);
            }
#pragma unroll
            for (int mt = 0; mt < 4; mt++)
#pragma unroll
                for (int nt = 0; nt < 4; nt++) {
                    const int bp = nt >> 1, bo = (nt & 1) * 2;
                    mma_fp16(acc[mt][nt], ah[mt], bh[bp][bo], bh[bp][bo + 1]);
                }
        }
    }

    // ---- epilogue: scr[slot][token][col] = w * (acc + be[e][col]), plain stores
    const int gid = lane >> 2;
    const int tig = lane & 3;
    const float* beRow = be + (size_t)e * DDIM + col0;
#pragma unroll
    for (int mt = 0; mt < 4; mt++) {
        const int  rA = m0 + mt * 16 + gid;
        const int  rB = rA + 8;
        const bool vA = rA < nvalid;
        const bool vB = rB < nvalid;
        const int  entA = ent_s[rA];
        const int  entB = ent_s[rB];
        const float wA = w_s[rA];
        const float wB = w_s[rB];
        float* sA = g_scr + ((size_t)(entA >> 1) + (size_t)(entA & 1) * TOKENS) * DDIM + col0;
        float* sB = g_scr + ((size_t)(entB >> 1) + (size_t)(entB & 1) * TOKENS) * DDIM + col0;
#pragma unroll
        for (int nt = 0; nt < 4; nt++) {
            const int c = n0w + nt * 8 + tig * 2;
            const float2 bev = *reinterpret_cast<const float2*>(beRow + c);
            if (vA) {
                float2 v = make_float2(wA * (acc[mt][nt][0] + bev.x),
                                       wA * (acc[mt][nt][1] + bev.y));
                *reinterpret_cast<float2*>(sA + c) = v;
            }
            if (vB) {
                float2 v = make_float2(wB * (acc[mt][nt][2] + bev.x),
                                       wB * (acc[mt][nt][3] + bev.y));
                *reinterpret_cast<float2*>(sB + c) = v;
            }
        }
    }
}

__global__ void combine_kernel(float* __restrict__ out) {
    const size_t i = (size_t)blockIdx.x * 256 + threadIdx.x;   // float4 units
    const float4* s = reinterpret_cast<const float4*>(g_scr);
    float4 a = s[i];
    float4 b = s[i + (size_t)TOKENS * DDIM / 4];
    a.x += b.x; a.y += b.y; a.z += b.z; a.w += b.w;
    reinterpret_cast<float4*>(out)[i] = a;
}

// ---------------- launch ----------------
extern "C" void kernel_launch(void* const* d_in, const int* in_sizes, int n_in,
                              void* d_out, int out_size) {
    const float* x  = (const float*)d_in[0];
    const float* Wg = (const float*)d_in[1];
    const float* bg = (const float*)d_in[2];
    const float* We = (const float*)d_in[3];
    const float* be = (const float*)d_in[4];
    float* out = (float*)d_out;

    cudaFuncSetAttribute(moe_gemm_mma, cudaFuncAttributeMaxDynamicSharedMemorySize, SMEM_TOTAL);

    prep_we_kernel<<<dim3(DDIM / 32, DDIM / 32, NEXP), 256>>>(We);   // also zeroes g_cnt
    gate_convert_kernel<<<TOKENS / 16, 256>>>(x, Wg, bg);            // fused gate + fp16

    dim3 grid(TOKENS / BM, DDIM / BN, NEXP);   // (64, 8, 8); empty row tiles early-exit
    moe_gemm_mma<<<grid, 256, SMEM_TOTAL>>>(be);

    combine_kernel<<<TOKENS * DDIM / 4 / 256, 256>>>(out);
}

// round 13
// speedup vs baseline: 1.2863x; 1.0381x over previous
#include <cuda_runtime.h>
#include <cuda_fp16.h>
#include <stdint.h>
#include <math.h>

#define TOKENS 8192
#define DDIM   1024
#define NEXP   8

#define BM 128
#define BN 128
#define BK 64
#define NKT (DDIM / BK)   // 16 k-chunks

#define GATE_BLOCKS (TOKENS / 16)            // 512
#define WE_BLOCKS   (32 * 32 * NEXP)         // 8192
#define PREP_BLOCKS (GATE_BLOCKS + WE_BLOCKS)

// ---------------- scratch (allocation-free rule: __device__ globals) ----------------
__device__ int   g_cnt[NEXP];                  // zero-init at load; re-zeroed by combine
__device__ int   g_tok[NEXP][TOKENS];          // packed: token*2 + slot
__device__ float g_wt [NEXP][TOKENS];
__device__ __half g_xh[TOKENS * DDIM];
__device__ __half g_Weh[NEXP * DDIM * DDIM];   // transposed: [e][n][k]
__device__ __half g_scrh[2 * TOKENS * DDIM];   // per-slot contributions (fp16)

// ---------------- helpers ----------------
__device__ __forceinline__ uint32_t smem_u32(const void* p) {
    uint32_t a;
    asm("{ .reg .u64 t; cvta.to.shared.u64 t, %1; cvt.u32.u64 %0, t; }" : "=r"(a) : "l"(p));
    return a;
}

// SW128 swizzle for 128B rows (Swizzle<3,4,3>)
#define SWZ(o) ((o) ^ (((o) >> 3) & 0x70))

__device__ __forceinline__ void ldsm_x4(uint32_t* r, uint32_t addr) {
    asm volatile("ldmatrix.sync.aligned.m8n8.x4.shared.b16 {%0,%1,%2,%3}, [%4];"
                 : "=r"(r[0]), "=r"(r[1]), "=r"(r[2]), "=r"(r[3]) : "r"(addr));
}

__device__ __forceinline__ void mma_fp16(float* c, const uint32_t* a, uint32_t b0, uint32_t b1) {
    asm volatile("mma.sync.aligned.m16n8k16.row.col.f32.f16.f16.f32 "
                 "{%0,%1,%2,%3}, {%4,%5,%6,%7}, {%8,%9}, {%0,%1,%2,%3};"
                 : "+f"(c[0]), "+f"(c[1]), "+f"(c[2]), "+f"(c[3])
                 : "r"(a[0]), "r"(a[1]), "r"(a[2]), "r"(a[3]), "r"(b0), "r"(b1));
}

#define CP_ASYNC16(dst, src) \
    asm volatile("cp.async.cg.shared.global [%0], [%1], 16;" :: "r"(dst), "l"(src))
#define CP_COMMIT() asm volatile("cp.async.commit_group;" ::: "memory")
#define CP_WAIT(n)  asm volatile("cp.async.wait_group %0;" :: "n"(n) : "memory")

// ---------------- SMEM layout (GEMM): 3 stages ----------------
#define SM_ENT   0
#define SM_W     512
#define SM_TILE  1024
#define A_BYTES  16384
#define STAGE_BYTES 32768
#define SMEM_TOTAL (SM_TILE + 3 * STAGE_BYTES)   // 99328; x2 CTAs = 198656 < 228KB

// ---------------- fused prep: gate+convert blocks || We transpose blocks ----------------
__global__ __launch_bounds__(256)
void prep_all_kernel(const float* __restrict__ x,
                     const float* __restrict__ Wg,
                     const float* __restrict__ bg,
                     const float* __restrict__ We) {
    if (blockIdx.x < GATE_BLOCKS) {
        // ---- gate + x fp32->fp16 (warp handles 2 tokens; Wg slab in registers) ----
        const int warp = threadIdx.x >> 5;
        const int lane = threadIdx.x & 31;
        const int t0 = (blockIdx.x * 8 + warp) * 2;

        float acc[2][NEXP];
#pragma unroll
        for (int tt = 0; tt < 2; tt++)
#pragma unroll
            for (int e = 0; e < NEXP; e++) acc[tt][e] = 0.f;

#pragma unroll
        for (int s = 0; s < 4; s++) {      // 4 slabs of 256 d
            float wg[8][NEXP];
#pragma unroll
            for (int i = 0; i < 8; i++) {
                const float4* wr = reinterpret_cast<const float4*>(
                    Wg + (size_t)(s * 256 + i * 32 + lane) * NEXP);
                float4 w0 = wr[0], w1 = wr[1];
                wg[i][0] = w0.x; wg[i][1] = w0.y; wg[i][2] = w0.z; wg[i][3] = w0.w;
                wg[i][4] = w1.x; wg[i][5] = w1.y; wg[i][6] = w1.z; wg[i][7] = w1.w;
            }
#pragma unroll
            for (int tt = 0; tt < 2; tt++) {
                const int dbase = s * 256 + lane;
                const float* xr = x + (size_t)(t0 + tt) * DDIM + dbase;
                __half*      xo = g_xh + (size_t)(t0 + tt) * DDIM + dbase;
#pragma unroll
                for (int i = 0; i < 8; i++) {
                    float xv = xr[i * 32];
                    xo[i * 32] = __float2half_rn(xv);
#pragma unroll
                    for (int e = 0; e < NEXP; e++) acc[tt][e] += xv * wg[i][e];
                }
            }
        }

#pragma unroll
        for (int tt = 0; tt < 2; tt++) {
            float v[NEXP];
#pragma unroll
            for (int e = 0; e < NEXP; e++) {
                float r = acc[tt][e];
#pragma unroll
                for (int o = 16; o > 0; o >>= 1) r += __shfl_down_sync(0xffffffffu, r, o);
                v[e] = r;
            }
            if (lane == 0) {
                float v1 = -INFINITY, v2 = -INFINITY;
                int   i1 = 0, i2 = 0;
#pragma unroll
                for (int e = 0; e < NEXP; e++) {
                    float s2 = v[e] + bg[e];
                    if (s2 > v1)      { v2 = v1; i2 = i1; v1 = s2; i1 = e; }
                    else if (s2 > v2) { v2 = s2; i2 = e; }
                }
                float l     = __expf(v2 - v1);
                float denom = 1.f + l;
                const int t = t0 + tt;
                int p1 = atomicAdd(&g_cnt[i1], 1);
                g_tok[i1][p1] = t * 2 + 0; g_wt[i1][p1] = 1.f / denom;
                int p2 = atomicAdd(&g_cnt[i2], 1);
                g_tok[i2][p2] = t * 2 + 1; g_wt[i2][p2] = l / denom;
            }
        }
    } else {
        // ---- We [e][k][n] fp32 -> transposed [e][n][k] fp16 via 32x32 smem tile ----
        __shared__ float s[32][33];
        const int idx = blockIdx.x - GATE_BLOCKS;
        const int n0 = (idx & 31) * 32;
        const int k0 = ((idx >> 5) & 31) * 32;
        const int e  = idx >> 10;
        const int tx = threadIdx.x & 31;
        const int ty = threadIdx.x >> 5;   // 0..7
        const float* src = We + ((size_t)e * DDIM + k0) * DDIM + n0;
#pragma unroll
        for (int i = 0; i < 4; i++)
            s[ty + i * 8][tx] = src[(size_t)(ty + i * 8) * DDIM + tx];
        __syncthreads();
#pragma unroll
        for (int i = 0; i < 4; i++) {
            const int nn = ty + i * 8;
            size_t o = ((size_t)e * DDIM + n0 + nn) * DDIM + k0 + tx;
            g_Weh[o] = __float2half_rn(s[tx][nn]);
        }
    }
}

// ---------------- HMMA grouped GEMM (fp16, 3-stage cp.async, warp-staggered ks) ----------
__global__ __launch_bounds__(256, 2)
void moe_gemm_mma(const float* __restrict__ be) {
    const int e    = blockIdx.z;
    const int n    = g_cnt[e];
    const int row0 = blockIdx.x * BM;
    if (row0 >= n) return;
    const int col0   = blockIdx.y * BN;
    const int nvalid = min(BM, n - row0);

    extern __shared__ char smem[];
    int*   ent_s = (int*)(smem + SM_ENT);
    float* w_s   = (float*)(smem + SM_W);
    const uint32_t tiles_u = smem_u32(smem + SM_TILE);

    const int tid  = threadIdx.x;
    const int lane = tid & 31;
    const int wid  = tid >> 5;

    if (tid < BM) {
        int tk = 0; float w = 0.f;
        if (tid < nvalid) { tk = g_tok[e][row0 + tid]; w = g_wt[e][row0 + tid]; }
        ent_s[tid] = tk;
        w_s[tid]   = w;
    }
    __syncthreads();

    // ---- staging: thread covers granules (sh..sh+3) of A row sr and B row sr
    const int sr = tid >> 1;
    const int sh = (tid & 1) * 4;
    uint32_t og[4];
#pragma unroll
    for (int q = 0; q < 4; q++)
        og[q] = SWZ((uint32_t)(sr * 128 + (sh + q) * 16));

    const __half* aS = g_xh + (size_t)(ent_s[sr] >> 1) * DDIM + sh * 8;
    const __half* bS = g_Weh + ((size_t)e * DDIM + col0 + sr) * DDIM + sh * 8;

    // ---- compute assignment: warp tile 64x32
    const int m0  = (wid & 1) * 64;
    const int n0w = (wid >> 1) * 32;
    const int a_lrow = (lane & 7) + ((lane >> 3) & 1) * 8;
    const int a_lk   = ((lane >> 4) & 1) * 8;
    const int b_lrow = (lane & 7) + ((lane >> 4) & 1) * 8;
    const int b_lk   = ((lane >> 3) & 1) * 8;

    float acc[4][4][4];
#pragma unroll
    for (int i = 0; i < 4; i++)
#pragma unroll
        for (int j = 0; j < 4; j++)
#pragma unroll
            for (int q = 0; q < 4; q++) acc[i][j][q] = 0.f;

    // prologue: stage chunks 0,1
#pragma unroll
    for (int pc = 0; pc < 2; pc++) {
        const uint32_t base = tiles_u + pc * STAGE_BYTES;
        const int kk = pc * BK;
#pragma unroll
        for (int q = 0; q < 4; q++) CP_ASYNC16(base + og[q], aS + kk + q * 8);
#pragma unroll
        for (int q = 0; q < 4; q++) CP_ASYNC16(base + A_BYTES + og[q], bS + kk + q * 8);
        CP_COMMIT();
    }

    const int ksPhase = wid & 3;   // de-phase warps: stagger ks order per warp

    for (int kt = 0; kt < NKT; kt++) {
        if (kt + 1 < NKT) { CP_WAIT(1); } else { CP_WAIT(0); }
        __syncthreads();   // chunk kt visible; all warps past chunk kt-1

        if (kt + 2 < NKT) {
            const uint32_t base = tiles_u + ((kt + 2) % 3) * STAGE_BYTES;
            const int kk = (kt + 2) * BK;
#pragma unroll
            for (int q = 0; q < 4; q++) CP_ASYNC16(base + og[q], aS + kk + q * 8);
#pragma unroll
            for (int q = 0; q < 4; q++) CP_ASYNC16(base + A_BYTES + og[q], bS + kk + q * 8);
            CP_COMMIT();
        }

        const uint32_t AU = tiles_u + (kt % 3) * STAGE_BYTES;
        const uint32_t BU = AU + A_BYTES;
#pragma unroll
        for (int ksi = 0; ksi < 4; ksi++) {
            const int ks = (ksi + ksPhase) & 3;    // rotated k-sub order (commutative)
            uint32_t ah[4][4], bh[2][4];
#pragma unroll
            for (int np = 0; np < 2; np++) {
                const uint32_t o = SWZ((uint32_t)((n0w + np * 16 + b_lrow) * 128 +
                                                  (ks * 16 + b_lk) * 2));
                ldsm_x4(bh[np], BU + o);
            }
#pragma unroll
            for (int mt = 0; mt < 4; mt++) {
                const uint32_t o = SWZ((uint32_t)((m0 + mt * 16 + a_lrow) * 128 +
                                                  (ks * 16 + a_lk) * 2));
                ldsm_x4(ah[mt], AU + o);
            }
#pragma unroll
            for (int mt = 0; mt < 4; mt++)
#pragma unroll
                for (int nt = 0; nt < 4; nt++) {
                    const int bp = nt >> 1, bo = (nt & 1) * 2;
                    mma_fp16(acc[mt][nt], ah[mt], bh[bp][bo], bh[bp][bo + 1]);
                }
        }
    }

    // ---- epilogue: scrh[slot][token][col] = fp16(w * (acc + be[e][col])) ----
    const int gid = lane >> 2;
    const int tig = lane & 3;
    const float* beRow = be + (size_t)e * DDIM + col0;
#pragma unroll
    for (int mt = 0; mt < 4; mt++) {
        const int  rA = m0 + mt * 16 + gid;
        const int  rB = rA + 8;
        const bool vA = rA < nvalid;
        const bool vB = rB < nvalid;
        const int  entA = ent_s[rA];
        const int  entB = ent_s[rB];
        const float wA = w_s[rA];
        const float wB = w_s[rB];
        __half* sA = g_scrh + ((size_t)(entA >> 1) + (size_t)(entA & 1) * TOKENS) * DDIM + col0;
        __half* sB = g_scrh + ((size_t)(entB >> 1) + (size_t)(entB & 1) * TOKENS) * DDIM + col0;
#pragma unroll
        for (int nt = 0; nt < 4; nt++) {
            const int c = n0w + nt * 8 + tig * 2;
            const float2 bev = *reinterpret_cast<const float2*>(beRow + c);
            if (vA) {
                __half2 h = __float22half2_rn(make_float2(wA * (acc[mt][nt][0] + bev.x),
                                                          wA * (acc[mt][nt][1] + bev.y)));
                *reinterpret_cast<__half2*>(sA + c) = h;
            }
            if (vB) {
                __half2 h = __float22half2_rn(make_float2(wB * (acc[mt][nt][2] + bev.x),
                                                          wB * (acc[mt][nt][3] + bev.y)));
                *reinterpret_cast<__half2*>(sB + c) = h;
            }
        }
    }
}

// combine slot contributions (fp16 -> fp32 sum) + re-zero g_cnt for the next call
__global__ void combine_kernel(float* __restrict__ out) {
    if (blockIdx.x == 0 && threadIdx.x < NEXP) g_cnt[threadIdx.x] = 0;
    const size_t i = (size_t)blockIdx.x * 256 + threadIdx.x;   // 4 floats each
    const uint2* s = reinterpret_cast<const uint2*>(g_scrh);
    uint2 a = s[i];
    uint2 b = s[i + (size_t)TOKENS * DDIM / 4];
    float2 a0 = __half22float2(*reinterpret_cast<__half2*>(&a.x));
    float2 a1 = __half22float2(*reinterpret_cast<__half2*>(&a.y));
    float2 b0 = __half22float2(*reinterpret_cast<__half2*>(&b.x));
    float2 b1 = __half22float2(*reinterpret_cast<__half2*>(&b.y));
    float4 r = make_float4(a0.x + b0.x, a0.y + b0.y, a1.x + b1.x, a1.y + b1.y);
    reinterpret_cast<float4*>(out)[i] = r;
}

// ---------------- launch ----------------
extern "C" void kernel_launch(void* const* d_in, const int* in_sizes, int n_in,
                              void* d_out, int out_size) {
    const float* x  = (const float*)d_in[0];
    const float* Wg = (const float*)d_in[1];
    const float* bg = (const float*)d_in[2];
    const float* We = (const float*)d_in[3];
    const float* be = (const float*)d_in[4];
    float* out = (float*)d_out;

    cudaFuncSetAttribute(moe_gemm_mma, cudaFuncAttributeMaxDynamicSharedMemorySize, SMEM_TOTAL);

    prep_all_kernel<<<PREP_BLOCKS, 256>>>(x, Wg, bg, We);   // gate+convert || We transpose

    dim3 grid(TOKENS / BM, DDIM / BN, NEXP);   // (64, 8, 8); empty row tiles early-exit
    moe_gemm_mma<<<grid, 256, SMEM_TOTAL>>>(be);

    combine_kernel<<<TOKENS * DDIM / 4 / 256, 256>>>(out);  // also re-zeroes g_cnt
}